// round 14
// baseline (speedup 1.0000x reference)
#include <cuda_runtime.h>
#include <math.h>
#include <stdint.h>

// Problem constants
#define Bsz   8
#define Ssz   2048
#define Hsz   8
#define Mrows (Bsz*Ssz*Hsz)    // 131072 rows (b,s,h)
#define Ktot  512
#define BSN   (Bsz*Ssz)
#define SSTRIDE 2048

// Scratch
__device__ float g_csum  [(size_t)Mrows*256];   // csum -> LN-normalized tf32, k-pair-permuted
__device__ float g_headstf[(size_t)Mrows*256];  // tf32 heads, k-pair-permuted
__device__ float g_f     [(size_t)Mrows*256];
__device__ float g_cell  [(size_t)Mrows*256];   // igh, then exact cell (linear)
__device__ float g_celltf[(size_t)Mrows*256];   // tf32 cell, k-pair-permuted
__device__ float g_Wp    [768*512];             // repacked+rounded W_hid, permuted
__device__ float g_Wog   [256*512];             // rounded W_og, permuted

__device__ __forceinline__ float sigmoidf_(float x) {
    return 1.0f / (1.0f + __expf(-x));
}
__device__ __forceinline__ float tfr(float x) {
    uint32_t u;
    asm("cvt.rna.tf32.f32 %0, %1;" : "=r"(u) : "f"(x));
    return __uint_as_float(u);
}
// k-pair permutation within 8-blocks: [k0,k4,k1,k5,k2,k6,k3,k7]
__device__ __forceinline__ int pk(int k) {
    return (k & ~7) | ((k & 3) << 1) | ((k >> 2) & 1);
}
#define MMA_TF32(d, a, b0, b1) \
    asm volatile("mma.sync.aligned.m16n8k8.row.col.f32.tf32.tf32.f32 " \
        "{%0,%1,%2,%3}, {%4,%5,%6,%7}, {%8,%9}, {%0,%1,%2,%3};" \
        : "+f"(d[0]), "+f"(d[1]), "+f"(d[2]), "+f"(d[3]) \
        : "r"(a[0]), "r"(a[1]), "r"(a[2]), "r"(a[3]), "r"(b0), "r"(b1))

#define CPA(dst, src) asm volatile("cp.async.cg.shared.global [%0], [%1], 16;" :: "r"(dst), "l"(src) : "memory")
#define CPC()         asm volatile("cp.async.commit_group;" ::: "memory")
#define CPW2()        asm volatile("cp.async.wait_group 2;" ::: "memory")

__device__ __forceinline__ uint32_t s2u(const void* p) {
    uint32_t a;
    asm("{ .reg .u64 t; cvta.to.shared.u64 t, %1; cvt.u32.u64 %0, t; }"
        : "=r"(a) : "l"(p));
    return a;
}

// ---------------------------------------------------------------------------
// cumsum over S per (b,h,id); emits permuted tf32 heads.
// ---------------------------------------------------------------------------
__global__ void cumsum_kernel(const float* __restrict__ x) {
    int lane = threadIdx.x;
    int r    = threadIdx.y;
    int idt  = blockIdx.x & 7;
    int h    = (blockIdx.x >> 3) & 7;
    int b    = blockIdx.x >> 6;
    int id   = idt * 32 + lane;
    size_t base  = (size_t)b * Ssz * SSTRIDE + (size_t)h * 256 + id;
    size_t basep = (size_t)b * Ssz * SSTRIDE + (size_t)h * 256 + pk(id);
    const int CH = Ssz / 16;

    size_t p = base + (size_t)(r * CH) * SSTRIDE;
    float sum = 0.f;
    #pragma unroll 8
    for (int i = 0; i < CH; i++) { sum += x[p]; p += SSTRIDE; }

    __shared__ float cs[16][32];
    cs[r][lane] = sum;
    __syncthreads();
    if (r == 0) {
        float a = 0.f;
        #pragma unroll
        for (int k2 = 0; k2 < 16; k2++) { float v = cs[k2][lane]; cs[k2][lane] = a; a += v; }
    }
    __syncthreads();

    float run = cs[r][lane];
    p = base + (size_t)(r * CH) * SSTRIDE;
    size_t pp = basep + (size_t)(r * CH) * SSTRIDE;
    #pragma unroll 8
    for (int i = 0; i < CH; i++) {
        float v = x[p];
        run += v;
        g_csum[p] = run;           // linear (stats reads linearly)
        g_headstf[pp] = tfr(v);    // permuted
        p += SSTRIDE; pp += SSTRIDE;
    }
}

// ---------------------------------------------------------------------------
// LayerNorm stats per (b,s) + in-place normalize of g_csum, writing the
// tf32-rounded result in k-pair-permuted order. Each thread owns one 8-block.
// ---------------------------------------------------------------------------
__global__ void stats_kernel(const float* __restrict__ lnw,
                             const float* __restrict__ lnb) {
    int bs = blockIdx.x;
    float4* p = (float4*)(g_csum + (size_t)bs * 2048);
    float s = 0.f, ss = 0.f;
    for (int i = threadIdx.x; i < 512; i += 256) {
        float4 v = p[i];
        s  += v.x + v.y + v.z + v.w;
        ss += v.x*v.x + v.y*v.y + v.z*v.z + v.w*v.w;
    }
    #pragma unroll
    for (int o = 16; o; o >>= 1) {
        s  += __shfl_down_sync(0xffffffffu, s,  o);
        ss += __shfl_down_sync(0xffffffffu, ss, o);
    }
    __shared__ float ws[8], wss[8];
    __shared__ float smu, srs;
    int wid = threadIdx.x >> 5, lane = threadIdx.x & 31;
    if (lane == 0) { ws[wid] = s; wss[wid] = ss; }
    __syncthreads();
    if (threadIdx.x == 0) {
        float S1 = 0.f, S2 = 0.f;
        #pragma unroll
        for (int i = 0; i < 8; i++) { S1 += ws[i]; S2 += wss[i]; }
        float mean = S1 * (1.f / 2048.f);
        float var  = S2 * (1.f / 2048.f) - mean * mean;
        smu = mean;
        srs = rsqrtf(var + 1e-6f);
    }
    __syncthreads();
    float mu = smu, rs = srs;
    const float4* w4 = (const float4*)lnw;
    const float4* b4 = (const float4*)lnb;
    int t = threadIdx.x;              // slice owner: floats 8t..8t+7
    float4 a = p[2*t], b = p[2*t+1];
    float4 wa = w4[2*t], wb = w4[2*t+1];
    float4 ba = b4[2*t], bb = b4[2*t+1];
    a.x = tfr((a.x - mu) * rs * wa.x + ba.x);
    a.y = tfr((a.y - mu) * rs * wa.y + ba.y);
    a.z = tfr((a.z - mu) * rs * wa.z + ba.z);
    a.w = tfr((a.w - mu) * rs * wa.w + ba.w);
    b.x = tfr((b.x - mu) * rs * wb.x + bb.x);
    b.y = tfr((b.y - mu) * rs * wb.y + bb.y);
    b.z = tfr((b.z - mu) * rs * wb.z + bb.z);
    b.w = tfr((b.w - mu) * rs * wb.w + bb.w);
    // permuted store: [k0,k4,k1,k5] [k2,k6,k3,k7]
    p[2*t]   = make_float4(a.x, b.x, a.y, b.y);
    p[2*t+1] = make_float4(a.z, b.z, a.w, b.w);
}

// ---------------------------------------------------------------------------
// Repack+round+permute W_hid: Wp[ob*192 + gate*64 + odl] row, k-pair order.
// 64 threads: one 8-float k-slice each.
// ---------------------------------------------------------------------------
__global__ void repack_kernel(const float* __restrict__ W) {
    int r = blockIdx.x;               // 0..767
    int ob = r / 192, rem = r % 192;
    int gate = rem / 64, odl = rem % 64;
    int src = gate * 256 + ob * 64 + odl;
    const float4* s = (const float4*)(W + (size_t)src * 512);
    float4* d = (float4*)(g_Wp + (size_t)r * 512);
    int t = threadIdx.x;
    float4 a = s[2*t], b = s[2*t+1];
    d[2*t]   = make_float4(tfr(a.x), tfr(b.x), tfr(a.y), tfr(b.y));
    d[2*t+1] = make_float4(tfr(a.z), tfr(b.z), tfr(a.w), tfr(b.w));
}
__global__ void repack_og(const float* __restrict__ W) {
    int r = blockIdx.x;               // 0..255
    const float4* s = (const float4*)(W + (size_t)r * 512);
    float4* d = (float4*)(g_Wog + (size_t)r * 512);
    int t = threadIdx.x;
    float4 a = s[2*t], b = s[2*t+1];
    d[2*t]   = make_float4(tfr(a.x), tfr(b.x), tfr(a.y), tfr(b.y));
    d[2*t+1] = make_float4(tfr(a.z), tfr(b.z), tfr(a.w), tfr(b.w));
}

// ---------------------------------------------------------------------------
// GEMM1 (mma.sync tf32, cp.async 3-stage, LDS.64 fragments):
// CTA 128m x 192n = {i|f|h} x 64 od.
// ---------------------------------------------------------------------------
#define G1_STAGE 40960              // 16384 A + 24576 B
#define G1_SMEM  (3*G1_STAGE)
__global__ __launch_bounds__(256)
void gemm1_t(const float* __restrict__ bias)
{
    extern __shared__ char smem[];
    uint32_t sb = s2u(smem);

    int t = threadIdx.x, w = t >> 5, lane = t & 31;
    int g = lane >> 2, tg = lane & 3;
    int wm = w >> 2, wn = w & 3;
    int ob = blockIdx.x;                 // od block 0..3
    int m0 = blockIdx.y * 128;
    int nbase = ob * 192;
    int gsw = (g & 3) << 2;              // pair-slot swizzle

    const char* srcAh[4]; const char* srcAc[4]; uint32_t dstA[4];
    const char* srcB[6];  uint32_t dstB[6];
    #pragma unroll
    for (int q = 0; q < 4; q++) {
        int gid = t + q * 256, row = gid >> 3, qc = gid & 7;
        srcAh[q] = (const char*)(g_headstf + (size_t)(m0 + row) * 256 + qc * 4);
        srcAc[q] = (const char*)(g_csum    + (size_t)(m0 + row) * 256 + qc * 4);
        dstA[q]  = row * 128 + ((qc ^ ((row & 3) << 1)) << 4);
    }
    #pragma unroll
    for (int q = 0; q < 6; q++) {
        int gid = t + q * 256, row = gid >> 3, qc = gid & 7;
        srcB[q] = (const char*)(g_Wp + (size_t)(nbase + row) * 512 + qc * 4);
        dstB[q] = row * 128 + ((qc ^ ((row & 3) << 1)) << 4);
    }

    auto issue = [&](int c) {
        uint32_t base = sb + (c % 3) * G1_STAGE;
        int k0 = c * 32;
        if (k0 < 256) {
            #pragma unroll
            for (int q = 0; q < 4; q++) CPA(base + dstA[q], srcAh[q] + (size_t)k0 * 4);
        } else {
            #pragma unroll
            for (int q = 0; q < 4; q++) CPA(base + dstA[q], srcAc[q] + (size_t)(k0 - 256) * 4);
        }
        uint32_t bb = base + 16384;
        #pragma unroll
        for (int q = 0; q < 6; q++) CPA(bb + dstB[q], srcB[q] + (size_t)k0 * 4);
        CPC();
    };

    float acc[4][6][4];
    #pragma unroll
    for (int i = 0; i < 4; i++)
        #pragma unroll
        for (int j = 0; j < 6; j++)
            #pragma unroll
            for (int k = 0; k < 4; k++) acc[i][j][k] = 0.f;

    issue(0); issue(1); issue(2);

    for (int c = 0; c < 16; c++) {
        CPW2();
        __syncthreads();
        const uint2* Ab2 = (const uint2*)(smem + (c % 3) * G1_STAGE);
        const uint2* Bb2 = (const uint2*)(smem + (c % 3) * G1_STAGE + 16384);
        #pragma unroll
        for (int ks = 0; ks < 4; ks++) {
            int s = (4 * ks + tg) ^ gsw;
            uint32_t af[4][4];
            #pragma unroll
            for (int fm = 0; fm < 4; fm++) {
                int r0 = (wm * 64 + fm * 16 + g) * 16;
                uint2 lo = Ab2[r0 + s];
                uint2 hi = Ab2[r0 + 128 + s];
                af[fm][0] = lo.x; af[fm][2] = lo.y;
                af[fm][1] = hi.x; af[fm][3] = hi.y;
            }
            #pragma unroll
            for (int fn = 0; fn < 6; fn++) {
                uint2 bp = Bb2[(wn * 48 + fn * 8 + g) * 16 + s];
                #pragma unroll
                for (int fm = 0; fm < 4; fm++)
                    MMA_TF32(acc[fm][fn], af[fm], bp.x, bp.y);
            }
        }
        __syncthreads();
        if (c + 3 < 16) issue(c + 3); else CPC();
    }

    // stage D to smem
    float* stage = (float*)smem;      // 128 x 200
    #pragma unroll
    for (int fm = 0; fm < 4; fm++) {
        int r0 = wm * 64 + fm * 16 + g;
        #pragma unroll
        for (int fn = 0; fn < 6; fn++) {
            int col = wn * 48 + fn * 8 + 2 * tg;
            *(float2*)&stage[r0 * 200 + col]       = make_float2(acc[fm][fn][0], acc[fm][fn][1]);
            *(float2*)&stage[(r0 + 8) * 200 + col] = make_float2(acc[fm][fn][2], acc[fm][fn][3]);
        }
    }
    __syncthreads();

    // epilogue: gates -> activations
    int row = t >> 1, half = (t & 1) * 32;
    int m = m0 + row;
    const float* sr = stage + row * 200;
    #pragma unroll
    for (int j = 0; j < 32; j += 4) {
        int odl = half + j;
        int od = ob * 64 + odl;
        float4 iv = *(const float4*)(sr + odl);
        float4 fv = *(const float4*)(sr + 64 + odl);
        float4 hv = *(const float4*)(sr + 128 + odl);
        float4 bi = *(const float4*)(bias + od);
        float4 bf = *(const float4*)(bias + 256 + od);
        float4 bh = *(const float4*)(bias + 512 + od);
        float4 fo, ig;
        fo.x = sigmoidf_(fv.x + bf.x);
        fo.y = sigmoidf_(fv.y + bf.y);
        fo.z = sigmoidf_(fv.z + bf.z);
        fo.w = sigmoidf_(fv.w + bf.w);
        ig.x = sigmoidf_(iv.x + bi.x) * fmaxf(hv.x + bh.x, 0.f);
        ig.y = sigmoidf_(iv.y + bi.y) * fmaxf(hv.y + bh.y, 0.f);
        ig.z = sigmoidf_(iv.z + bi.z) * fmaxf(hv.z + bh.z, 0.f);
        ig.w = sigmoidf_(iv.w + bi.w) * fmaxf(hv.w + bh.w, 0.f);
        *(float4*)(g_f    + (size_t)m * 256 + od) = fo;
        *(float4*)(g_cell + (size_t)m * 256 + od) = ig;
    }
}

// ---------------------------------------------------------------------------
// GEMM2 (mma.sync tf32, cp.async 3-stage, LDS.64 fragments): CTA 128m x 128n.
// ---------------------------------------------------------------------------
#define G2_STAGE 32768              // 16384 A + 16384 B
#define G2_SMEM  (3*G2_STAGE)
__global__ __launch_bounds__(256)
void gemm2_t(const float* __restrict__ bias, float* __restrict__ out)
{
    extern __shared__ char smem[];
    uint32_t sb = s2u(smem);

    int t = threadIdx.x, w = t >> 5, lane = t & 31;
    int g = lane >> 2, tg = lane & 3;
    int wm = w >> 2, wn = w & 3;
    int n0 = blockIdx.x * 128;
    int m0 = blockIdx.y * 128;
    int gsw = (g & 3) << 2;

    const char* srcAh[4]; const char* srcAc[4]; const char* srcB[4];
    uint32_t dstQ[4];
    #pragma unroll
    for (int q = 0; q < 4; q++) {
        int gid = t + q * 256, row = gid >> 3, qc = gid & 7;
        srcAh[q] = (const char*)(g_headstf + (size_t)(m0 + row) * 256 + qc * 4);
        srcAc[q] = (const char*)(g_celltf  + (size_t)(m0 + row) * 256 + qc * 4);
        srcB[q]  = (const char*)(g_Wog + (size_t)(n0 + row) * 512 + qc * 4);
        dstQ[q]  = row * 128 + ((qc ^ ((row & 3) << 1)) << 4);
    }

    auto issue = [&](int c) {
        uint32_t base = sb + (c % 3) * G2_STAGE;
        int k0 = c * 32;
        if (k0 < 256) {
            #pragma unroll
            for (int q = 0; q < 4; q++) CPA(base + dstQ[q], srcAh[q] + (size_t)k0 * 4);
        } else {
            #pragma unroll
            for (int q = 0; q < 4; q++) CPA(base + dstQ[q], srcAc[q] + (size_t)(k0 - 256) * 4);
        }
        uint32_t bb = base + 16384;
        #pragma unroll
        for (int q = 0; q < 4; q++) CPA(bb + dstQ[q], srcB[q] + (size_t)k0 * 4);
        CPC();
    };

    float acc[4][4][4];
    #pragma unroll
    for (int i = 0; i < 4; i++)
        #pragma unroll
        for (int j = 0; j < 4; j++)
            #pragma unroll
            for (int k = 0; k < 4; k++) acc[i][j][k] = 0.f;

    issue(0); issue(1); issue(2);

    for (int c = 0; c < 16; c++) {
        CPW2();
        __syncthreads();
        const uint2* Ab2 = (const uint2*)(smem + (c % 3) * G2_STAGE);
        const uint2* Bb2 = (const uint2*)(smem + (c % 3) * G2_STAGE + 16384);
        #pragma unroll
        for (int ks = 0; ks < 4; ks++) {
            int s = (4 * ks + tg) ^ gsw;
            uint32_t af[4][4];
            #pragma unroll
            for (int fm = 0; fm < 4; fm++) {
                int r0 = (wm * 64 + fm * 16 + g) * 16;
                uint2 lo = Ab2[r0 + s];
                uint2 hi = Ab2[r0 + 128 + s];
                af[fm][0] = lo.x; af[fm][2] = lo.y;
                af[fm][1] = hi.x; af[fm][3] = hi.y;
            }
            #pragma unroll
            for (int fn = 0; fn < 4; fn++) {
                uint2 bp = Bb2[(wn * 32 + fn * 8 + g) * 16 + s];
                #pragma unroll
                for (int fm = 0; fm < 4; fm++)
                    MMA_TF32(acc[fm][fn], af[fm], bp.x, bp.y);
            }
        }
        __syncthreads();
        if (c + 3 < 16) issue(c + 3); else CPC();
    }

    // stage D to smem
    float* stage = (float*)smem;      // 128 x 136
    #pragma unroll
    for (int fm = 0; fm < 4; fm++) {
        int r0 = wm * 64 + fm * 16 + g;
        #pragma unroll
        for (int fn = 0; fn < 4; fn++) {
            int col = wn * 32 + fn * 8 + 2 * tg;
            *(float2*)&stage[r0 * 136 + col]       = make_float2(acc[fm][fn][0], acc[fm][fn][1]);
            *(float2*)&stage[(r0 + 8) * 136 + col] = make_float2(acc[fm][fn][2], acc[fm][fn][3]);
        }
    }
    __syncthreads();

    // epilogue
    int row = t >> 1, half = (t & 1) * 64;
    int m = m0 + row;
    const float* sr = stage + row * 136;
    #pragma unroll
    for (int j = 0; j < 64; j += 4) {
        int col = half + j;
        int od = n0 + col;
        float4 dv = *(const float4*)(sr + col);
        float4 bb = *(const float4*)(bias + od);
        float4 cl = *(const float4*)(g_cell + (size_t)m * 256 + od);
        float4 v;
        v.x = sigmoidf_(dv.x + bb.x) * cl.x;
        v.y = sigmoidf_(dv.y + bb.y) * cl.y;
        v.z = sigmoidf_(dv.z + bb.z) * cl.z;
        v.w = sigmoidf_(dv.w + bb.w) * cl.w;
        *(float4*)(out + (size_t)m * 256 + od) = v;
    }
}

// ---------------------------------------------------------------------------
// Scan: c <- f*c + igh over S; writes exact cell (linear) + permuted tf32 cell.
// ---------------------------------------------------------------------------
__global__ void scan_kernel(const float* __restrict__ init_cx) {
    int lane = threadIdx.x;
    int r    = threadIdx.y;
    int idt  = blockIdx.x & 7;
    int h    = (blockIdx.x >> 3) & 7;
    int b    = blockIdx.x >> 6;
    int od   = idt * 32 + lane;
    size_t base  = (size_t)b * Ssz * SSTRIDE + (size_t)h * 256 + od;
    size_t basep = (size_t)b * Ssz * SSTRIDE + (size_t)h * 256 + pk(od);
    const int CH = Ssz / 16;

    size_t p = base + (size_t)(r * CH) * SSTRIDE;
    float F = 1.f, I = 0.f;
    #pragma unroll 8
    for (int i = 0; i < CH; i++) {
        float f = g_f[p], ig = g_cell[p];
        I = fmaf(f, I, ig);
        F *= f;
        p += SSTRIDE;
    }
    __shared__ float sF[16][32], sI[16][32];
    sF[r][lane] = F; sI[r][lane] = I;
    __syncthreads();
    if (r == 0) {
        float c = init_cx[h * 256 + od];
        #pragma unroll
        for (int k2 = 0; k2 < 16; k2++) {
            float nf = sF[k2][lane], ni = sI[k2][lane];
            sI[k2][lane] = c;
            c = fmaf(nf, c, ni);
        }
    }
    __syncthreads();
    float c = sI[r][lane];
    p = base + (size_t)(r * CH) * SSTRIDE;
    size_t pp = basep + (size_t)(r * CH) * SSTRIDE;
    #pragma unroll 8
    for (int i = 0; i < CH; i++) {
        float f = g_f[p], ig = g_cell[p];
        c = fmaf(f, c, ig);
        g_cell[p] = c;
        g_celltf[pp] = tfr(c);
        p += SSTRIDE; pp += SSTRIDE;
    }
}

// ---------------------------------------------------------------------------
extern "C" void kernel_launch(void* const* d_in, const int* in_sizes, int n_in,
                              void* d_out, int out_size)
{
    const float* heads   = (const float*)d_in[0];
    const float* W_hid   = (const float*)d_in[1];
    const float* b_hid   = (const float*)d_in[2];
    const float* W_og    = (const float*)d_in[3];
    const float* b_og    = (const float*)d_in[4];
    const float* ln_w    = (const float*)d_in[5];
    const float* ln_b    = (const float*)d_in[6];
    const float* init_cx = (const float*)d_in[7];
    float* out = (float*)d_out;

    cudaFuncSetAttribute(gemm1_t, cudaFuncAttributeMaxDynamicSharedMemorySize, G1_SMEM);
    cudaFuncSetAttribute(gemm2_t, cudaFuncAttributeMaxDynamicSharedMemorySize, G2_SMEM);

    repack_kernel<<<768, 64>>>(W_hid);
    repack_og<<<256, 64>>>(W_og);
    cumsum_kernel<<<512, dim3(32, 16)>>>(heads);
    stats_kernel<<<BSN, 256>>>(ln_w, ln_b);
    gemm1_t<<<dim3(4, Mrows / 128), 256, G1_SMEM>>>(b_hid);
    scan_kernel<<<512, dim3(32, 16)>>>(init_cx);
    gemm2_t<<<dim3(2, Mrows / 128), 256, G2_SMEM>>>(b_og, out);
}

// round 15
// speedup vs baseline: 1.1441x; 1.1441x over previous
#include <cuda_runtime.h>
#include <math.h>
#include <stdint.h>

// Problem constants
#define Bsz   8
#define Ssz   2048
#define Hsz   8
#define Mrows (Bsz*Ssz*Hsz)    // 131072 rows (b,s,h)
#define Ktot  512
#define BSN   (Bsz*Ssz)
#define SSTRIDE 2048

// Scratch
__device__ float g_csum  [(size_t)Mrows*256];   // csum -> LN-normalized tf32
__device__ float g_headstf[(size_t)Mrows*256];  // tf32-rounded heads
__device__ float g_f     [(size_t)Mrows*256];
__device__ float g_cell  [(size_t)Mrows*256];   // igh, then exact cell
__device__ float g_celltf[(size_t)Mrows*256];   // tf32-rounded cell
__device__ float g_Wp    [768*512];             // repacked+rounded W_hid
__device__ float g_Wog   [256*512];             // rounded W_og

__device__ __forceinline__ float sigmoidf_(float x) {
    return 1.0f / (1.0f + __expf(-x));
}
__device__ __forceinline__ float tfr(float x) {
    uint32_t u;
    asm("cvt.rna.tf32.f32 %0, %1;" : "=r"(u) : "f"(x));
    return __uint_as_float(u);
}
#define MMA_TF32(d, a, b0, b1) \
    asm volatile("mma.sync.aligned.m16n8k8.row.col.f32.tf32.tf32.f32 " \
        "{%0,%1,%2,%3}, {%4,%5,%6,%7}, {%8,%9}, {%0,%1,%2,%3};" \
        : "+f"(d[0]), "+f"(d[1]), "+f"(d[2]), "+f"(d[3]) \
        : "r"(a[0]), "r"(a[1]), "r"(a[2]), "r"(a[3]), "r"(b0), "r"(b1))

#define CPA(dst, src) asm volatile("cp.async.cg.shared.global [%0], [%1], 16;" :: "r"(dst), "l"(src) : "memory")
#define CPC()         asm volatile("cp.async.commit_group;" ::: "memory")
#define CPW2()        asm volatile("cp.async.wait_group 2;" ::: "memory")
#define CPW1()        asm volatile("cp.async.wait_group 1;" ::: "memory")

__device__ __forceinline__ uint32_t s2u(const void* p) {
    uint32_t a;
    asm("{ .reg .u64 t; cvta.to.shared.u64 t, %1; cvt.u32.u64 %0, t; }"
        : "=r"(a) : "l"(p));
    return a;
}

// ---------------------------------------------------------------------------
// cumsum over S per (b,h,id); also emits tf32-rounded heads.
// ---------------------------------------------------------------------------
__global__ void cumsum_kernel(const float* __restrict__ x) {
    int lane = threadIdx.x;
    int r    = threadIdx.y;
    int idt  = blockIdx.x & 7;
    int h    = (blockIdx.x >> 3) & 7;
    int b    = blockIdx.x >> 6;
    int id   = idt * 32 + lane;
    size_t base = (size_t)b * Ssz * SSTRIDE + (size_t)h * 256 + id;
    const int CH = Ssz / 16;

    size_t p = base + (size_t)(r * CH) * SSTRIDE;
    float sum = 0.f;
    #pragma unroll 8
    for (int i = 0; i < CH; i++) { sum += x[p]; p += SSTRIDE; }

    __shared__ float cs[16][32];
    cs[r][lane] = sum;
    __syncthreads();
    if (r == 0) {
        float a = 0.f;
        #pragma unroll
        for (int k2 = 0; k2 < 16; k2++) { float v = cs[k2][lane]; cs[k2][lane] = a; a += v; }
    }
    __syncthreads();

    float run = cs[r][lane];
    p = base + (size_t)(r * CH) * SSTRIDE;
    #pragma unroll 8
    for (int i = 0; i < CH; i++) {
        float v = x[p];
        run += v;
        g_csum[p] = run;
        g_headstf[p] = tfr(v);
        p += SSTRIDE;
    }
}

// ---------------------------------------------------------------------------
// LayerNorm stats per (b,s) + in-place normalize (tf32-rounded) of g_csum.
// ---------------------------------------------------------------------------
__global__ void stats_kernel(const float* __restrict__ lnw,
                             const float* __restrict__ lnb) {
    int bs = blockIdx.x;
    float4* p = (float4*)(g_csum + (size_t)bs * 2048);
    float s = 0.f, ss = 0.f;
    for (int i = threadIdx.x; i < 512; i += 256) {
        float4 v = p[i];
        s  += v.x + v.y + v.z + v.w;
        ss += v.x*v.x + v.y*v.y + v.z*v.z + v.w*v.w;
    }
    #pragma unroll
    for (int o = 16; o; o >>= 1) {
        s  += __shfl_down_sync(0xffffffffu, s,  o);
        ss += __shfl_down_sync(0xffffffffu, ss, o);
    }
    __shared__ float ws[8], wss[8];
    __shared__ float smu, srs;
    int wid = threadIdx.x >> 5, lane = threadIdx.x & 31;
    if (lane == 0) { ws[wid] = s; wss[wid] = ss; }
    __syncthreads();
    if (threadIdx.x == 0) {
        float S1 = 0.f, S2 = 0.f;
        #pragma unroll
        for (int i = 0; i < 8; i++) { S1 += ws[i]; S2 += wss[i]; }
        float mean = S1 * (1.f / 2048.f);
        float var  = S2 * (1.f / 2048.f) - mean * mean;
        smu = mean;
        srs = rsqrtf(var + 1e-6f);
    }
    __syncthreads();
    float mu = smu, rs = srs;
    const float4* w4 = (const float4*)lnw;
    const float4* b4 = (const float4*)lnb;
    for (int i = threadIdx.x; i < 512; i += 256) {
        float4 v = p[i], w = w4[i], b = b4[i];
        v.x = tfr((v.x - mu) * rs * w.x + b.x);
        v.y = tfr((v.y - mu) * rs * w.y + b.y);
        v.z = tfr((v.z - mu) * rs * w.z + b.z);
        v.w = tfr((v.w - mu) * rs * w.w + b.w);
        p[i] = v;
    }
}

// ---------------------------------------------------------------------------
// Repack+round W_hid: Wp[ob*192 + gate*64 + odl] = W_hid[gate*256 + ob*64 + odl]
// ---------------------------------------------------------------------------
__global__ void repack_kernel(const float* __restrict__ W) {
    int r = blockIdx.x;               // 0..767
    int ob = r / 192, rem = r % 192;
    int gate = rem / 64, odl = rem % 64;
    int src = gate * 256 + ob * 64 + odl;
    const float4* s = (const float4*)(W + (size_t)src * 512);
    float4* d = (float4*)(g_Wp + (size_t)r * 512);
    float4 v = s[threadIdx.x];
    v.x = tfr(v.x); v.y = tfr(v.y); v.z = tfr(v.z); v.w = tfr(v.w);
    d[threadIdx.x] = v;
}
__global__ void repack_og(const float* __restrict__ W) {
    int r = blockIdx.x;               // 0..255
    const float4* s = (const float4*)(W + (size_t)r * 512);
    float4* d = (float4*)(g_Wog + (size_t)r * 512);
    float4 v = s[threadIdx.x];
    v.x = tfr(v.x); v.y = tfr(v.y); v.z = tfr(v.z); v.w = tfr(v.w);
    d[threadIdx.x] = v;
}

// ---------------------------------------------------------------------------
// GEMM1 (mma.sync tf32, cp.async 3-stage): CTA 128m x 192n = {i|f|h} x 64 od.
// Warp n-columns remapped so each thread holds all 3 gates for its od pairs:
//   col(fn) = (fn>>1)*64 + wn*16 + (fn&1)*8   (gate = fn>>1, odp = fn&1)
// Register-direct epilogue -> g_f, g_cell (no smem staging).
// ---------------------------------------------------------------------------
#define G1_STAGE 40960              // 16384 A + 24576 B
#define G1_SMEM  (3*G1_STAGE)
__global__ __launch_bounds__(256)
void gemm1_t(const float* __restrict__ bias)
{
    extern __shared__ char smem[];
    uint32_t sb = s2u(smem);

    int t = threadIdx.x, w = t >> 5, lane = t & 31;
    int g = lane >> 2, tg = lane & 3;
    int wm = w >> 2, wn = w & 3;
    int ob = blockIdx.x;                 // od block 0..3
    int m0 = blockIdx.y * 128;
    int nbase = ob * 192;

    const char* srcAh[4]; const char* srcAc[4]; uint32_t dstA[4];
    const char* srcB[6];  uint32_t dstB[6];
    #pragma unroll
    for (int q = 0; q < 4; q++) {
        int gid = t + q * 256, row = gid >> 3, qc = gid & 7;
        srcAh[q] = (const char*)(g_headstf + (size_t)(m0 + row) * 256 + qc * 4);
        srcAc[q] = (const char*)(g_csum    + (size_t)(m0 + row) * 256 + qc * 4);
        dstA[q]  = row * 128 + ((qc ^ (row & 7)) << 4);
    }
    #pragma unroll
    for (int q = 0; q < 6; q++) {
        int gid = t + q * 256, row = gid >> 3, qc = gid & 7;
        srcB[q] = (const char*)(g_Wp + (size_t)(nbase + row) * 512 + qc * 4);
        dstB[q] = row * 128 + ((qc ^ (row & 7)) << 4);
    }

    auto issue = [&](int c) {
        uint32_t base = sb + (c % 3) * G1_STAGE;
        int k0 = c * 32;
        if (k0 < 256) {
            #pragma unroll
            for (int q = 0; q < 4; q++) CPA(base + dstA[q], srcAh[q] + (size_t)k0 * 4);
        } else {
            #pragma unroll
            for (int q = 0; q < 4; q++) CPA(base + dstA[q], srcAc[q] + (size_t)(k0 - 256) * 4);
        }
        uint32_t bb = base + 16384;
        #pragma unroll
        for (int q = 0; q < 6; q++) CPA(bb + dstB[q], srcB[q] + (size_t)k0 * 4);
        CPC();
    };

    float acc[4][6][4];
    #pragma unroll
    for (int i = 0; i < 4; i++)
        #pragma unroll
        for (int j = 0; j < 6; j++)
            #pragma unroll
            for (int k = 0; k < 4; k++) acc[i][j][k] = 0.f;

    issue(0); issue(1); issue(2);

    for (int c = 0; c < 16; c++) {
        CPW2();
        __syncthreads();
        const uint32_t* Ab = (const uint32_t*)(smem + (c % 3) * G1_STAGE);
        const uint32_t* Bb = (const uint32_t*)(smem + (c % 3) * G1_STAGE + 16384);
        #pragma unroll
        for (int ks = 0; ks < 4; ks++) {
            int c0 = (((2 * ks)     ^ g) << 2) + tg;
            int c1 = (((2 * ks + 1) ^ g) << 2) + tg;
            uint32_t af[4][4];
            #pragma unroll
            for (int fm = 0; fm < 4; fm++) {
                int base = (wm * 64 + fm * 16 + g) * 32;
                af[fm][0] = Ab[base + c0];
                af[fm][1] = Ab[base + 256 + c0];
                af[fm][2] = Ab[base + c1];
                af[fm][3] = Ab[base + 256 + c1];
            }
            #pragma unroll
            for (int fn = 0; fn < 6; fn++) {
                // gate-grouped n map: all 3 gates of od-block wn*16 live in this warp
                int col = (fn >> 1) * 64 + wn * 16 + ((fn & 1) << 3);
                int nb = (col + g) * 32;
                uint32_t b0 = Bb[nb + c0], b1 = Bb[nb + c1];
                #pragma unroll
                for (int fm = 0; fm < 4; fm++)
                    MMA_TF32(acc[fm][fn], af[fm], b0, b1);
            }
        }
        __syncthreads();
        if (c + 3 < 16) issue(c + 3); else CPC();
    }

    // register-direct epilogue: thread holds i/f/h for rows (r, r+8), od pairs
    #pragma unroll
    for (int odp = 0; odp < 2; odp++) {
        int od = ob * 64 + wn * 16 + odp * 8 + 2 * tg;
        float2 bi = *(const float2*)(bias + od);
        float2 bf = *(const float2*)(bias + 256 + od);
        float2 bh = *(const float2*)(bias + 512 + od);
        #pragma unroll
        for (int fm = 0; fm < 4; fm++) {
            #pragma unroll
            for (int rsel = 0; rsel < 2; rsel++) {
                int m = m0 + wm * 64 + fm * 16 + g + rsel * 8;
                float iv0 = acc[fm][0 + odp][rsel * 2 + 0];
                float iv1 = acc[fm][0 + odp][rsel * 2 + 1];
                float fv0 = acc[fm][2 + odp][rsel * 2 + 0];
                float fv1 = acc[fm][2 + odp][rsel * 2 + 1];
                float hv0 = acc[fm][4 + odp][rsel * 2 + 0];
                float hv1 = acc[fm][4 + odp][rsel * 2 + 1];
                float2 fo, ig;
                fo.x = sigmoidf_(fv0 + bf.x);
                fo.y = sigmoidf_(fv1 + bf.y);
                ig.x = sigmoidf_(iv0 + bi.x) * fmaxf(hv0 + bh.x, 0.f);
                ig.y = sigmoidf_(iv1 + bi.y) * fmaxf(hv1 + bh.y, 0.f);
                *(float2*)(g_f    + (size_t)m * 256 + od) = fo;
                *(float2*)(g_cell + (size_t)m * 256 + od) = ig;
            }
        }
    }
}

// ---------------------------------------------------------------------------
// GEMM2 (mma.sync tf32, cp.async 2-stage, 2 CTAs/SM): CTA 128m x 128n.
// Register-direct epilogue: out = sigmoid(D + b) * cell (exact cell from gmem).
// ---------------------------------------------------------------------------
#define G2_STAGE 32768              // 16384 A + 16384 B
#define G2_SMEM  (2*G2_STAGE)       // 65536 -> 2 CTAs/SM
__global__ __launch_bounds__(256, 2)
void gemm2_t(const float* __restrict__ bias, float* __restrict__ out)
{
    extern __shared__ char smem[];
    uint32_t sb = s2u(smem);

    int t = threadIdx.x, w = t >> 5, lane = t & 31;
    int g = lane >> 2, tg = lane & 3;
    int wm = w >> 2, wn = w & 3;
    int n0 = blockIdx.x * 128;
    int m0 = blockIdx.y * 128;

    const char* srcAh[4]; const char* srcAc[4]; const char* srcB[4];
    uint32_t dstQ[4];
    #pragma unroll
    for (int q = 0; q < 4; q++) {
        int gid = t + q * 256, row = gid >> 3, qc = gid & 7;
        srcAh[q] = (const char*)(g_headstf + (size_t)(m0 + row) * 256 + qc * 4);
        srcAc[q] = (const char*)(g_celltf  + (size_t)(m0 + row) * 256 + qc * 4);
        srcB[q]  = (const char*)(g_Wog + (size_t)(n0 + row) * 512 + qc * 4);
        dstQ[q]  = row * 128 + ((qc ^ (row & 7)) << 4);
    }

    auto issue = [&](int c) {
        uint32_t base = sb + (c & 1) * G2_STAGE;
        int k0 = c * 32;
        if (k0 < 256) {
            #pragma unroll
            for (int q = 0; q < 4; q++) CPA(base + dstQ[q], srcAh[q] + (size_t)k0 * 4);
        } else {
            #pragma unroll
            for (int q = 0; q < 4; q++) CPA(base + dstQ[q], srcAc[q] + (size_t)(k0 - 256) * 4);
        }
        uint32_t bb = base + 16384;
        #pragma unroll
        for (int q = 0; q < 4; q++) CPA(bb + dstQ[q], srcB[q] + (size_t)k0 * 4);
        CPC();
    };

    float acc[4][4][4];
    #pragma unroll
    for (int i = 0; i < 4; i++)
        #pragma unroll
        for (int j = 0; j < 4; j++)
            #pragma unroll
            for (int k = 0; k < 4; k++) acc[i][j][k] = 0.f;

    issue(0); issue(1);

    for (int c = 0; c < 16; c++) {
        CPW1();
        __syncthreads();
        const uint32_t* Ab = (const uint32_t*)(smem + (c & 1) * G2_STAGE);
        const uint32_t* Bb = (const uint32_t*)(smem + (c & 1) * G2_STAGE + 16384);
        #pragma unroll
        for (int ks = 0; ks < 4; ks++) {
            int c0 = (((2 * ks)     ^ g) << 2) + tg;
            int c1 = (((2 * ks + 1) ^ g) << 2) + tg;
            uint32_t af[4][4];
            #pragma unroll
            for (int fm = 0; fm < 4; fm++) {
                int base = (wm * 64 + fm * 16 + g) * 32;
                af[fm][0] = Ab[base + c0];
                af[fm][1] = Ab[base + 256 + c0];
                af[fm][2] = Ab[base + c1];
                af[fm][3] = Ab[base + 256 + c1];
            }
            #pragma unroll
            for (int fn = 0; fn < 4; fn++) {
                int nb = (wn * 32 + fn * 8 + g) * 32;
                uint32_t b0 = Bb[nb + c0], b1 = Bb[nb + c1];
                #pragma unroll
                for (int fm = 0; fm < 4; fm++)
                    MMA_TF32(acc[fm][fn], af[fm], b0, b1);
            }
        }
        __syncthreads();
        // always commit exactly one group per iteration (tail keeps wait valid)
        if (c + 2 < 16) issue(c + 2); else CPC();
    }

    // register-direct epilogue
    #pragma unroll
    for (int fn = 0; fn < 4; fn++) {
        int od = n0 + wn * 32 + fn * 8 + 2 * tg;
        float2 bb = *(const float2*)(bias + od);
        #pragma unroll
        for (int fm = 0; fm < 4; fm++) {
            #pragma unroll
            for (int rsel = 0; rsel < 2; rsel++) {
                int m = m0 + wm * 64 + fm * 16 + g + rsel * 8;
                float2 cl = *(const float2*)(g_cell + (size_t)m * 256 + od);
                float2 v;
                v.x = sigmoidf_(acc[fm][fn][rsel * 2 + 0] + bb.x) * cl.x;
                v.y = sigmoidf_(acc[fm][fn][rsel * 2 + 1] + bb.y) * cl.y;
                *(float2*)(out + (size_t)m * 256 + od) = v;
            }
        }
    }
}

// ---------------------------------------------------------------------------
// Scan: c <- f*c + igh over S; writes exact cell and tf32-rounded cell.
// ---------------------------------------------------------------------------
__global__ void scan_kernel(const float* __restrict__ init_cx) {
    int lane = threadIdx.x;
    int r    = threadIdx.y;
    int idt  = blockIdx.x & 7;
    int h    = (blockIdx.x >> 3) & 7;
    int b    = blockIdx.x >> 6;
    int od   = idt * 32 + lane;
    size_t base = (size_t)b * Ssz * SSTRIDE + (size_t)h * 256 + od;
    const int CH = Ssz / 16;

    size_t p = base + (size_t)(r * CH) * SSTRIDE;
    float F = 1.f, I = 0.f;
    #pragma unroll 8
    for (int i = 0; i < CH; i++) {
        float f = g_f[p], ig = g_cell[p];
        I = fmaf(f, I, ig);
        F *= f;
        p += SSTRIDE;
    }
    __shared__ float sF[16][32], sI[16][32];
    sF[r][lane] = F; sI[r][lane] = I;
    __syncthreads();
    if (r == 0) {
        float c = init_cx[h * 256 + od];
        #pragma unroll
        for (int k2 = 0; k2 < 16; k2++) {
            float nf = sF[k2][lane], ni = sI[k2][lane];
            sI[k2][lane] = c;
            c = fmaf(nf, c, ni);
        }
    }
    __syncthreads();
    float c = sI[r][lane];
    p = base + (size_t)(r * CH) * SSTRIDE;
    #pragma unroll 8
    for (int i = 0; i < CH; i++) {
        float f = g_f[p], ig = g_cell[p];
        c = fmaf(f, c, ig);
        g_cell[p] = c;
        g_celltf[p] = tfr(c);
        p += SSTRIDE;
    }
}

// ---------------------------------------------------------------------------
extern "C" void kernel_launch(void* const* d_in, const int* in_sizes, int n_in,
                              void* d_out, int out_size)
{
    const float* heads   = (const float*)d_in[0];
    const float* W_hid   = (const float*)d_in[1];
    const float* b_hid   = (const float*)d_in[2];
    const float* W_og    = (const float*)d_in[3];
    const float* b_og    = (const float*)d_in[4];
    const float* ln_w    = (const float*)d_in[5];
    const float* ln_b    = (const float*)d_in[6];
    const float* init_cx = (const float*)d_in[7];
    float* out = (float*)d_out;

    cudaFuncSetAttribute(gemm1_t, cudaFuncAttributeMaxDynamicSharedMemorySize, G1_SMEM);
    cudaFuncSetAttribute(gemm2_t, cudaFuncAttributeMaxDynamicSharedMemorySize, G2_SMEM);

    repack_kernel<<<768, 128>>>(W_hid);
    repack_og<<<256, 128>>>(W_og);
    cumsum_kernel<<<512, dim3(32, 16)>>>(heads);
    stats_kernel<<<BSN, 256>>>(ln_w, ln_b);
    gemm1_t<<<dim3(4, Mrows / 128), 256, G1_SMEM>>>(b_hid);
    scan_kernel<<<512, dim3(32, 16)>>>(init_cx);
    gemm2_t<<<dim3(2, Mrows / 128), 256, G2_SMEM>>>(b_og, out);
}

// round 16
// speedup vs baseline: 1.1488x; 1.0041x over previous
#include <cuda_runtime.h>
#include <math.h>
#include <stdint.h>

// Problem constants
#define Bsz   8
#define Ssz   2048
#define Hsz   8
#define Mrows (Bsz*Ssz*Hsz)    // 131072 rows (b,s,h)
#define Ktot  512
#define BSN   (Bsz*Ssz)
#define SSTRIDE 2048

// Scratch
__device__ float g_csum  [(size_t)Mrows*256];   // csum -> LN-normalized tf32
__device__ float g_headstf[(size_t)Mrows*256];  // tf32-rounded heads
__device__ float g_f     [(size_t)Mrows*256];
__device__ float g_cell  [(size_t)Mrows*256];   // igh, then exact cell
__device__ float g_celltf[(size_t)Mrows*256];   // tf32-rounded cell
__device__ float g_Wp    [768*512];             // repacked+rounded W_hid
__device__ float g_Wog   [256*512];             // rounded W_og

__device__ __forceinline__ float sigmoidf_(float x) {
    return 1.0f / (1.0f + __expf(-x));
}
__device__ __forceinline__ float tfr(float x) {
    uint32_t u;
    asm("cvt.rna.tf32.f32 %0, %1;" : "=r"(u) : "f"(x));
    return __uint_as_float(u);
}
#define MMA_TF32(d, a, b0, b1) \
    asm volatile("mma.sync.aligned.m16n8k8.row.col.f32.tf32.tf32.f32 " \
        "{%0,%1,%2,%3}, {%4,%5,%6,%7}, {%8,%9}, {%0,%1,%2,%3};" \
        : "+f"(d[0]), "+f"(d[1]), "+f"(d[2]), "+f"(d[3]) \
        : "r"(a[0]), "r"(a[1]), "r"(a[2]), "r"(a[3]), "r"(b0), "r"(b1))

#define CPA(dst, src) asm volatile("cp.async.cg.shared.global [%0], [%1], 16;" :: "r"(dst), "l"(src) : "memory")
#define CPC()         asm volatile("cp.async.commit_group;" ::: "memory")
#define CPW2()        asm volatile("cp.async.wait_group 2;" ::: "memory")
#define CPW1()        asm volatile("cp.async.wait_group 1;" ::: "memory")

__device__ __forceinline__ uint32_t s2u(const void* p) {
    uint32_t a;
    asm("{ .reg .u64 t; cvta.to.shared.u64 t, %1; cvt.u32.u64 %0, t; }"
        : "=r"(a) : "l"(p));
    return a;
}

// ---------------------------------------------------------------------------
// cumsum over S per (b,h,id); also emits tf32-rounded heads.
// ---------------------------------------------------------------------------
__global__ void cumsum_kernel(const float* __restrict__ x) {
    int lane = threadIdx.x;
    int r    = threadIdx.y;
    int idt  = blockIdx.x & 7;
    int h    = (blockIdx.x >> 3) & 7;
    int b    = blockIdx.x >> 6;
    int id   = idt * 32 + lane;
    size_t base = (size_t)b * Ssz * SSTRIDE + (size_t)h * 256 + id;
    const int CH = Ssz / 16;

    size_t p = base + (size_t)(r * CH) * SSTRIDE;
    float sum = 0.f;
    #pragma unroll 8
    for (int i = 0; i < CH; i++) { sum += x[p]; p += SSTRIDE; }

    __shared__ float cs[16][32];
    cs[r][lane] = sum;
    __syncthreads();
    if (r == 0) {
        float a = 0.f;
        #pragma unroll
        for (int k2 = 0; k2 < 16; k2++) { float v = cs[k2][lane]; cs[k2][lane] = a; a += v; }
    }
    __syncthreads();

    float run = cs[r][lane];
    p = base + (size_t)(r * CH) * SSTRIDE;
    #pragma unroll 8
    for (int i = 0; i < CH; i++) {
        float v = x[p];
        run += v;
        g_csum[p] = run;
        g_headstf[p] = tfr(v);
        p += SSTRIDE;
    }
}

// ---------------------------------------------------------------------------
// LayerNorm stats per (b,s) + in-place normalize (tf32-rounded) of g_csum.
// ---------------------------------------------------------------------------
__global__ void stats_kernel(const float* __restrict__ lnw,
                             const float* __restrict__ lnb) {
    int bs = blockIdx.x;
    float4* p = (float4*)(g_csum + (size_t)bs * 2048);
    float s = 0.f, ss = 0.f;
    for (int i = threadIdx.x; i < 512; i += 256) {
        float4 v = p[i];
        s  += v.x + v.y + v.z + v.w;
        ss += v.x*v.x + v.y*v.y + v.z*v.z + v.w*v.w;
    }
    #pragma unroll
    for (int o = 16; o; o >>= 1) {
        s  += __shfl_down_sync(0xffffffffu, s,  o);
        ss += __shfl_down_sync(0xffffffffu, ss, o);
    }
    __shared__ float ws[8], wss[8];
    __shared__ float smu, srs;
    int wid = threadIdx.x >> 5, lane = threadIdx.x & 31;
    if (lane == 0) { ws[wid] = s; wss[wid] = ss; }
    __syncthreads();
    if (threadIdx.x == 0) {
        float S1 = 0.f, S2 = 0.f;
        #pragma unroll
        for (int i = 0; i < 8; i++) { S1 += ws[i]; S2 += wss[i]; }
        float mean = S1 * (1.f / 2048.f);
        float var  = S2 * (1.f / 2048.f) - mean * mean;
        smu = mean;
        srs = rsqrtf(var + 1e-6f);
    }
    __syncthreads();
    float mu = smu, rs = srs;
    const float4* w4 = (const float4*)lnw;
    const float4* b4 = (const float4*)lnb;
    for (int i = threadIdx.x; i < 512; i += 256) {
        float4 v = p[i], w = w4[i], b = b4[i];
        v.x = tfr((v.x - mu) * rs * w.x + b.x);
        v.y = tfr((v.y - mu) * rs * w.y + b.y);
        v.z = tfr((v.z - mu) * rs * w.z + b.z);
        v.w = tfr((v.w - mu) * rs * w.w + b.w);
        p[i] = v;
    }
}

// ---------------------------------------------------------------------------
// Repack+round W_hid: Wp[ob*192 + gate*64 + odl] = W_hid[gate*256 + ob*64 + odl]
// ---------------------------------------------------------------------------
__global__ void repack_kernel(const float* __restrict__ W) {
    int r = blockIdx.x;               // 0..767
    int ob = r / 192, rem = r % 192;
    int gate = rem / 64, odl = rem % 64;
    int src = gate * 256 + ob * 64 + odl;
    const float4* s = (const float4*)(W + (size_t)src * 512);
    float4* d = (float4*)(g_Wp + (size_t)r * 512);
    float4 v = s[threadIdx.x];
    v.x = tfr(v.x); v.y = tfr(v.y); v.z = tfr(v.z); v.w = tfr(v.w);
    d[threadIdx.x] = v;
}
__global__ void repack_og(const float* __restrict__ W) {
    int r = blockIdx.x;               // 0..255
    const float4* s = (const float4*)(W + (size_t)r * 512);
    float4* d = (float4*)(g_Wog + (size_t)r * 512);
    float4 v = s[threadIdx.x];
    v.x = tfr(v.x); v.y = tfr(v.y); v.z = tfr(v.z); v.w = tfr(v.w);
    d[threadIdx.x] = v;
}

// ---------------------------------------------------------------------------
// GEMM1 (mma.sync tf32, cp.async 3-stage, 512 threads / 16 warps):
// CTA 128m x 192n = {i|f|h} x 64 od. Warp tile 32m x 48n (wm 0..3, wn 0..3).
// Gate-grouped n map: col(fn) = (fn>>1)*64 + wn*16 + (fn&1)*8.
// Register-direct epilogue -> g_f, g_cell.
// ---------------------------------------------------------------------------
#define G1_STAGE 40960              // 16384 A + 24576 B
#define G1_SMEM  (3*G1_STAGE)
__global__ __launch_bounds__(512)
void gemm1_t(const float* __restrict__ bias)
{
    extern __shared__ char smem[];
    uint32_t sb = s2u(smem);

    int t = threadIdx.x, w = t >> 5, lane = t & 31;
    int g = lane >> 2, tg = lane & 3;
    int wm = w >> 2, wn = w & 3;          // wm 0..3 (32m each), wn 0..3
    int ob = blockIdx.x;                  // od block 0..3
    int m0 = blockIdx.y * 128;
    int nbase = ob * 192;

    // cp.async mappings: A = 1024 float4 (2/thread), B = 1536 float4 (3/thread)
    const char* srcAh[2]; const char* srcAc[2]; uint32_t dstA[2];
    const char* srcB[3];  uint32_t dstB[3];
    #pragma unroll
    for (int q = 0; q < 2; q++) {
        int gid = t + q * 512, row = gid >> 3, qc = gid & 7;
        srcAh[q] = (const char*)(g_headstf + (size_t)(m0 + row) * 256 + qc * 4);
        srcAc[q] = (const char*)(g_csum    + (size_t)(m0 + row) * 256 + qc * 4);
        dstA[q]  = row * 128 + ((qc ^ (row & 7)) << 4);
    }
    #pragma unroll
    for (int q = 0; q < 3; q++) {
        int gid = t + q * 512, row = gid >> 3, qc = gid & 7;
        srcB[q] = (const char*)(g_Wp + (size_t)(nbase + row) * 512 + qc * 4);
        dstB[q] = row * 128 + ((qc ^ (row & 7)) << 4);
    }

    auto issue = [&](int c) {
        uint32_t base = sb + (c % 3) * G1_STAGE;
        int k0 = c * 32;
        if (k0 < 256) {
            #pragma unroll
            for (int q = 0; q < 2; q++) CPA(base + dstA[q], srcAh[q] + (size_t)k0 * 4);
        } else {
            #pragma unroll
            for (int q = 0; q < 2; q++) CPA(base + dstA[q], srcAc[q] + (size_t)(k0 - 256) * 4);
        }
        uint32_t bb = base + 16384;
        #pragma unroll
        for (int q = 0; q < 3; q++) CPA(bb + dstB[q], srcB[q] + (size_t)k0 * 4);
        CPC();
    };

    float acc[2][6][4];
    #pragma unroll
    for (int i = 0; i < 2; i++)
        #pragma unroll
        for (int j = 0; j < 6; j++)
            #pragma unroll
            for (int k = 0; k < 4; k++) acc[i][j][k] = 0.f;

    issue(0); issue(1); issue(2);

    for (int c = 0; c < 16; c++) {
        CPW2();
        __syncthreads();
        const uint32_t* Ab = (const uint32_t*)(smem + (c % 3) * G1_STAGE);
        const uint32_t* Bb = (const uint32_t*)(smem + (c % 3) * G1_STAGE + 16384);
        #pragma unroll
        for (int ks = 0; ks < 4; ks++) {
            int c0 = (((2 * ks)     ^ g) << 2) + tg;
            int c1 = (((2 * ks + 1) ^ g) << 2) + tg;
            uint32_t af[2][4];
            #pragma unroll
            for (int fm = 0; fm < 2; fm++) {
                int base = (wm * 32 + fm * 16 + g) * 32;
                af[fm][0] = Ab[base + c0];
                af[fm][1] = Ab[base + 256 + c0];
                af[fm][2] = Ab[base + c1];
                af[fm][3] = Ab[base + 256 + c1];
            }
            #pragma unroll
            for (int fn = 0; fn < 6; fn++) {
                int col = (fn >> 1) * 64 + wn * 16 + ((fn & 1) << 3);
                int nb = (col + g) * 32;
                uint32_t b0 = Bb[nb + c0], b1 = Bb[nb + c1];
                #pragma unroll
                for (int fm = 0; fm < 2; fm++)
                    MMA_TF32(acc[fm][fn], af[fm], b0, b1);
            }
        }
        __syncthreads();
        if (c + 3 < 16) issue(c + 3); else CPC();
    }

    // register-direct epilogue: thread holds i/f/h for rows (r, r+8), od pairs
    #pragma unroll
    for (int odp = 0; odp < 2; odp++) {
        int od = ob * 64 + wn * 16 + odp * 8 + 2 * tg;
        float2 bi = *(const float2*)(bias + od);
        float2 bf = *(const float2*)(bias + 256 + od);
        float2 bh = *(const float2*)(bias + 512 + od);
        #pragma unroll
        for (int fm = 0; fm < 2; fm++) {
            #pragma unroll
            for (int rsel = 0; rsel < 2; rsel++) {
                int m = m0 + wm * 32 + fm * 16 + g + rsel * 8;
                float iv0 = acc[fm][0 + odp][rsel * 2 + 0];
                float iv1 = acc[fm][0 + odp][rsel * 2 + 1];
                float fv0 = acc[fm][2 + odp][rsel * 2 + 0];
                float fv1 = acc[fm][2 + odp][rsel * 2 + 1];
                float hv0 = acc[fm][4 + odp][rsel * 2 + 0];
                float hv1 = acc[fm][4 + odp][rsel * 2 + 1];
                float2 fo, ig;
                fo.x = sigmoidf_(fv0 + bf.x);
                fo.y = sigmoidf_(fv1 + bf.y);
                ig.x = sigmoidf_(iv0 + bi.x) * fmaxf(hv0 + bh.x, 0.f);
                ig.y = sigmoidf_(iv1 + bi.y) * fmaxf(hv1 + bh.y, 0.f);
                *(float2*)(g_f    + (size_t)m * 256 + od) = fo;
                *(float2*)(g_cell + (size_t)m * 256 + od) = ig;
            }
        }
    }
}

// ---------------------------------------------------------------------------
// GEMM2 (mma.sync tf32, cp.async 2-stage, 2 CTAs/SM): CTA 128m x 128n.
// Register-direct epilogue: out = sigmoid(D + b) * cell (exact cell from gmem).
// ---------------------------------------------------------------------------
#define G2_STAGE 32768              // 16384 A + 16384 B
#define G2_SMEM  (2*G2_STAGE)       // 65536 -> 2 CTAs/SM
__global__ __launch_bounds__(256, 2)
void gemm2_t(const float* __restrict__ bias, float* __restrict__ out)
{
    extern __shared__ char smem[];
    uint32_t sb = s2u(smem);

    int t = threadIdx.x, w = t >> 5, lane = t & 31;
    int g = lane >> 2, tg = lane & 3;
    int wm = w >> 2, wn = w & 3;
    int n0 = blockIdx.x * 128;
    int m0 = blockIdx.y * 128;

    const char* srcAh[4]; const char* srcAc[4]; const char* srcB[4];
    uint32_t dstQ[4];
    #pragma unroll
    for (int q = 0; q < 4; q++) {
        int gid = t + q * 256, row = gid >> 3, qc = gid & 7;
        srcAh[q] = (const char*)(g_headstf + (size_t)(m0 + row) * 256 + qc * 4);
        srcAc[q] = (const char*)(g_celltf  + (size_t)(m0 + row) * 256 + qc * 4);
        srcB[q]  = (const char*)(g_Wog + (size_t)(n0 + row) * 512 + qc * 4);
        dstQ[q]  = row * 128 + ((qc ^ (row & 7)) << 4);
    }

    auto issue = [&](int c) {
        uint32_t base = sb + (c & 1) * G2_STAGE;
        int k0 = c * 32;
        if (k0 < 256) {
            #pragma unroll
            for (int q = 0; q < 4; q++) CPA(base + dstQ[q], srcAh[q] + (size_t)k0 * 4);
        } else {
            #pragma unroll
            for (int q = 0; q < 4; q++) CPA(base + dstQ[q], srcAc[q] + (size_t)(k0 - 256) * 4);
        }
        uint32_t bb = base + 16384;
        #pragma unroll
        for (int q = 0; q < 4; q++) CPA(bb + dstQ[q], srcB[q] + (size_t)k0 * 4);
        CPC();
    };

    float acc[4][4][4];
    #pragma unroll
    for (int i = 0; i < 4; i++)
        #pragma unroll
        for (int j = 0; j < 4; j++)
            #pragma unroll
            for (int k = 0; k < 4; k++) acc[i][j][k] = 0.f;

    issue(0); issue(1);

    for (int c = 0; c < 16; c++) {
        CPW1();
        __syncthreads();
        const uint32_t* Ab = (const uint32_t*)(smem + (c & 1) * G2_STAGE);
        const uint32_t* Bb = (const uint32_t*)(smem + (c & 1) * G2_STAGE + 16384);
        #pragma unroll
        for (int ks = 0; ks < 4; ks++) {
            int c0 = (((2 * ks)     ^ g) << 2) + tg;
            int c1 = (((2 * ks + 1) ^ g) << 2) + tg;
            uint32_t af[4][4];
            #pragma unroll
            for (int fm = 0; fm < 4; fm++) {
                int base = (wm * 64 + fm * 16 + g) * 32;
                af[fm][0] = Ab[base + c0];
                af[fm][1] = Ab[base + 256 + c0];
                af[fm][2] = Ab[base + c1];
                af[fm][3] = Ab[base + 256 + c1];
            }
            #pragma unroll
            for (int fn = 0; fn < 4; fn++) {
                int nb = (wn * 32 + fn * 8 + g) * 32;
                uint32_t b0 = Bb[nb + c0], b1 = Bb[nb + c1];
                #pragma unroll
                for (int fm = 0; fm < 4; fm++)
                    MMA_TF32(acc[fm][fn], af[fm], b0, b1);
            }
        }
        __syncthreads();
        if (c + 2 < 16) issue(c + 2); else CPC();
    }

    // register-direct epilogue
    #pragma unroll
    for (int fn = 0; fn < 4; fn++) {
        int od = n0 + wn * 32 + fn * 8 + 2 * tg;
        float2 bb = *(const float2*)(bias + od);
        #pragma unroll
        for (int fm = 0; fm < 4; fm++) {
            #pragma unroll
            for (int rsel = 0; rsel < 2; rsel++) {
                int m = m0 + wm * 64 + fm * 16 + g + rsel * 8;
                float2 cl = *(const float2*)(g_cell + (size_t)m * 256 + od);
                float2 v;
                v.x = sigmoidf_(acc[fm][fn][rsel * 2 + 0] + bb.x) * cl.x;
                v.y = sigmoidf_(acc[fm][fn][rsel * 2 + 1] + bb.y) * cl.y;
                *(float2*)(out + (size_t)m * 256 + od) = v;
            }
        }
    }
}

// ---------------------------------------------------------------------------
// Scan: c <- f*c + igh over S; writes exact cell and tf32-rounded cell.
// ---------------------------------------------------------------------------
__global__ void scan_kernel(const float* __restrict__ init_cx) {
    int lane = threadIdx.x;
    int r    = threadIdx.y;
    int idt  = blockIdx.x & 7;
    int h    = (blockIdx.x >> 3) & 7;
    int b    = blockIdx.x >> 6;
    int od   = idt * 32 + lane;
    size_t base = (size_t)b * Ssz * SSTRIDE + (size_t)h * 256 + od;
    const int CH = Ssz / 16;

    size_t p = base + (size_t)(r * CH) * SSTRIDE;
    float F = 1.f, I = 0.f;
    #pragma unroll 8
    for (int i = 0; i < CH; i++) {
        float f = g_f[p], ig = g_cell[p];
        I = fmaf(f, I, ig);
        F *= f;
        p += SSTRIDE;
    }
    __shared__ float sF[16][32], sI[16][32];
    sF[r][lane] = F; sI[r][lane] = I;
    __syncthreads();
    if (r == 0) {
        float c = init_cx[h * 256 + od];
        #pragma unroll
        for (int k2 = 0; k2 < 16; k2++) {
            float nf = sF[k2][lane], ni = sI[k2][lane];
            sI[k2][lane] = c;
            c = fmaf(nf, c, ni);
        }
    }
    __syncthreads();
    float c = sI[r][lane];
    p = base + (size_t)(r * CH) * SSTRIDE;
    #pragma unroll 8
    for (int i = 0; i < CH; i++) {
        float f = g_f[p], ig = g_cell[p];
        c = fmaf(f, c, ig);
        g_cell[p] = c;
        g_celltf[p] = tfr(c);
        p += SSTRIDE;
    }
}

// ---------------------------------------------------------------------------
extern "C" void kernel_launch(void* const* d_in, const int* in_sizes, int n_in,
                              void* d_out, int out_size)
{
    const float* heads   = (const float*)d_in[0];
    const float* W_hid   = (const float*)d_in[1];
    const float* b_hid   = (const float*)d_in[2];
    const float* W_og    = (const float*)d_in[3];
    const float* b_og    = (const float*)d_in[4];
    const float* ln_w    = (const float*)d_in[5];
    const float* ln_b    = (const float*)d_in[6];
    const float* init_cx = (const float*)d_in[7];
    float* out = (float*)d_out;

    cudaFuncSetAttribute(gemm1_t, cudaFuncAttributeMaxDynamicSharedMemorySize, G1_SMEM);
    cudaFuncSetAttribute(gemm2_t, cudaFuncAttributeMaxDynamicSharedMemorySize, G2_SMEM);

    repack_kernel<<<768, 128>>>(W_hid);
    repack_og<<<256, 128>>>(W_og);
    cumsum_kernel<<<512, dim3(32, 16)>>>(heads);
    stats_kernel<<<BSN, 256>>>(ln_w, ln_b);
    gemm1_t<<<dim3(4, Mrows / 128), 512, G1_SMEM>>>(b_hid);
    scan_kernel<<<512, dim3(32, 16)>>>(init_cx);
    gemm2_t<<<dim3(2, Mrows / 128), 256, G2_SMEM>>>(b_og, out);
}

// round 17
// speedup vs baseline: 1.5368x; 1.3378x over previous
#include <cuda_runtime.h>
#include <cuda_fp16.h>
#include <math.h>
#include <stdint.h>

// Problem constants
#define Bsz   8
#define Ssz   2048
#define Hsz   8
#define Mrows (Bsz*Ssz*Hsz)    // 131072 rows (b,s,h)
#define Ktot  512
#define BSN   (Bsz*Ssz)
#define SSTRIDE 2048

// Scratch
__device__ float  g_csum  [(size_t)Mrows*256];   // raw csum (stats input)
__device__ __half g_headshf[(size_t)Mrows*256];  // fp16 heads
__device__ __half g_csumhf [(size_t)Mrows*256];  // fp16 LN(csum)
__device__ float  g_f     [(size_t)Mrows*256];
__device__ float  g_cell  [(size_t)Mrows*256];   // igh, then exact cell
__device__ __half g_cellhf[(size_t)Mrows*256];   // fp16 cell
__device__ __half g_Wp    [768*512];             // repacked fp16 W_hid
__device__ __half g_Wog   [256*512];             // fp16 W_og

__device__ __forceinline__ float sigmoidf_(float x) {
    return 1.0f / (1.0f + __expf(-x));
}
#define MMA_F16(d, a, b0, b1) \
    asm volatile("mma.sync.aligned.m16n8k16.row.col.f32.f16.f16.f32 " \
        "{%0,%1,%2,%3}, {%4,%5,%6,%7}, {%8,%9}, {%0,%1,%2,%3};" \
        : "+f"(d[0]), "+f"(d[1]), "+f"(d[2]), "+f"(d[3]) \
        : "r"(a[0]), "r"(a[1]), "r"(a[2]), "r"(a[3]), "r"(b0), "r"(b1))

#define CPA(dst, src) asm volatile("cp.async.cg.shared.global [%0], [%1], 16;" :: "r"(dst), "l"(src) : "memory")
#define CPC()         asm volatile("cp.async.commit_group;" ::: "memory")
#define CPW2()        asm volatile("cp.async.wait_group 2;" ::: "memory")
#define CPW1()        asm volatile("cp.async.wait_group 1;" ::: "memory")

__device__ __forceinline__ uint32_t s2u(const void* p) {
    uint32_t a;
    asm("{ .reg .u64 t; cvta.to.shared.u64 t, %1; cvt.u32.u64 %0, t; }"
        : "=r"(a) : "l"(p));
    return a;
}

// ---------------------------------------------------------------------------
// cumsum over S per (b,h,id); also emits fp16 heads.
// ---------------------------------------------------------------------------
__global__ void cumsum_kernel(const float* __restrict__ x) {
    int lane = threadIdx.x;
    int r    = threadIdx.y;
    int idt  = blockIdx.x & 7;
    int h    = (blockIdx.x >> 3) & 7;
    int b    = blockIdx.x >> 6;
    int id   = idt * 32 + lane;
    size_t base = (size_t)b * Ssz * SSTRIDE + (size_t)h * 256 + id;
    const int CH = Ssz / 16;

    size_t p = base + (size_t)(r * CH) * SSTRIDE;
    float sum = 0.f;
    #pragma unroll 8
    for (int i = 0; i < CH; i++) { sum += x[p]; p += SSTRIDE; }

    __shared__ float cs[16][32];
    cs[r][lane] = sum;
    __syncthreads();
    if (r == 0) {
        float a = 0.f;
        #pragma unroll
        for (int k2 = 0; k2 < 16; k2++) { float v = cs[k2][lane]; cs[k2][lane] = a; a += v; }
    }
    __syncthreads();

    float run = cs[r][lane];
    p = base + (size_t)(r * CH) * SSTRIDE;
    #pragma unroll 8
    for (int i = 0; i < CH; i++) {
        float v = x[p];
        run += v;
        g_csum[p] = run;
        g_headshf[p] = __float2half_rn(v);
        p += SSTRIDE;
    }
}

// ---------------------------------------------------------------------------
// LayerNorm stats per (b,s); normalize csum and emit fp16.
// ---------------------------------------------------------------------------
__global__ void stats_kernel(const float* __restrict__ lnw,
                             const float* __restrict__ lnb) {
    int bs = blockIdx.x;
    const float4* p = (const float4*)(g_csum + (size_t)bs * 2048);
    __half2* o = (__half2*)(g_csumhf + (size_t)bs * 2048);
    float s = 0.f, ss = 0.f;
    for (int i = threadIdx.x; i < 512; i += 256) {
        float4 v = p[i];
        s  += v.x + v.y + v.z + v.w;
        ss += v.x*v.x + v.y*v.y + v.z*v.z + v.w*v.w;
    }
    #pragma unroll
    for (int o2 = 16; o2; o2 >>= 1) {
        s  += __shfl_down_sync(0xffffffffu, s,  o2);
        ss += __shfl_down_sync(0xffffffffu, ss, o2);
    }
    __shared__ float ws[8], wss[8];
    __shared__ float smu, srs;
    int wid = threadIdx.x >> 5, lane = threadIdx.x & 31;
    if (lane == 0) { ws[wid] = s; wss[wid] = ss; }
    __syncthreads();
    if (threadIdx.x == 0) {
        float S1 = 0.f, S2 = 0.f;
        #pragma unroll
        for (int i = 0; i < 8; i++) { S1 += ws[i]; S2 += wss[i]; }
        float mean = S1 * (1.f / 2048.f);
        float var  = S2 * (1.f / 2048.f) - mean * mean;
        smu = mean;
        srs = rsqrtf(var + 1e-6f);
    }
    __syncthreads();
    float mu = smu, rs = srs;
    const float4* w4 = (const float4*)lnw;
    const float4* b4 = (const float4*)lnb;
    for (int i = threadIdx.x; i < 512; i += 256) {
        float4 v = p[i], w = w4[i], b = b4[i];
        o[2*i]   = __floats2half2_rn((v.x - mu) * rs * w.x + b.x,
                                     (v.y - mu) * rs * w.y + b.y);
        o[2*i+1] = __floats2half2_rn((v.z - mu) * rs * w.z + b.z,
                                     (v.w - mu) * rs * w.w + b.w);
    }
}

// ---------------------------------------------------------------------------
// Repack W_hid -> fp16: Wp[ob*192 + gate*64 + odl] = W_hid[gate*256+ob*64+odl]
// ---------------------------------------------------------------------------
__global__ void repack_kernel(const float* __restrict__ W) {
    int r = blockIdx.x;               // 0..767
    int ob = r / 192, rem = r % 192;
    int gate = rem / 64, odl = rem % 64;
    int src = gate * 256 + ob * 64 + odl;
    const float4* s = (const float4*)(W + (size_t)src * 512);
    __half2* d = (__half2*)(g_Wp + (size_t)r * 512);
    float4 v = s[threadIdx.x];
    d[2*threadIdx.x]   = __floats2half2_rn(v.x, v.y);
    d[2*threadIdx.x+1] = __floats2half2_rn(v.z, v.w);
}
__global__ void repack_og(const float* __restrict__ W) {
    int r = blockIdx.x;               // 0..255
    const float4* s = (const float4*)(W + (size_t)r * 512);
    __half2* d = (__half2*)(g_Wog + (size_t)r * 512);
    float4 v = s[threadIdx.x];
    d[2*threadIdx.x]   = __floats2half2_rn(v.x, v.y);
    d[2*threadIdx.x+1] = __floats2half2_rn(v.z, v.w);
}

// ---------------------------------------------------------------------------
// GEMM1 (mma.sync fp16 m16n8k16, cp.async 3-stage, 256 thr):
// CTA 128m x 192n = {i|f|h} x 64 od; gate-grouped n map; reg-direct epilogue.
// smem tile rows: 16 uint32 (32 halves) per row, swizzle col ^ ((row&6)<<1).
// ---------------------------------------------------------------------------
#define G1_STAGE 20480              // 8192 A + 12288 B
#define G1_SMEM  (3*G1_STAGE)
__global__ __launch_bounds__(256)
void gemm1_t(const float* __restrict__ bias)
{
    extern __shared__ char smem[];
    uint32_t sb = s2u(smem);

    int t = threadIdx.x, w = t >> 5, lane = t & 31;
    int g = lane >> 2, tg = lane & 3;
    int wm = w >> 2, wn = w & 3;
    int ob = blockIdx.x;                 // od block 0..3
    int m0 = blockIdx.y * 128;
    int nbase = ob * 192;
    int sw = (g & 6) << 1;

    // cp.async: A = 512 float4 (2/thread), B = 768 float4 (3/thread)
    const char* srcAh[2]; const char* srcAc[2]; uint32_t dstA[2];
    const char* srcB[3];  uint32_t dstB[3];
    #pragma unroll
    for (int q = 0; q < 2; q++) {
        int gid = t + q * 256, row = gid >> 2, qc = gid & 3;
        srcAh[q] = (const char*)(g_headshf + (size_t)(m0 + row) * 256 + qc * 8);
        srcAc[q] = (const char*)(g_csumhf  + (size_t)(m0 + row) * 256 + qc * 8);
        dstA[q]  = row * 64 + ((qc << 4) ^ ((row & 6) << 3));
    }
    #pragma unroll
    for (int q = 0; q < 3; q++) {
        int gid = t + q * 256, row = gid >> 2, qc = gid & 3;
        srcB[q] = (const char*)(g_Wp + (size_t)(nbase + row) * 512 + qc * 8);
        dstB[q] = row * 64 + ((qc << 4) ^ ((row & 6) << 3));
    }

    auto issue = [&](int c) {
        uint32_t base = sb + (c % 3) * G1_STAGE;
        int k0 = c * 32;
        if (k0 < 256) {
            #pragma unroll
            for (int q = 0; q < 2; q++) CPA(base + dstA[q], srcAh[q] + (size_t)k0 * 2);
        } else {
            #pragma unroll
            for (int q = 0; q < 2; q++) CPA(base + dstA[q], srcAc[q] + (size_t)(k0 - 256) * 2);
        }
        uint32_t bb = base + 8192;
        #pragma unroll
        for (int q = 0; q < 3; q++) CPA(bb + dstB[q], srcB[q] + (size_t)k0 * 2);
        CPC();
    };

    float acc[4][6][4];
    #pragma unroll
    for (int i = 0; i < 4; i++)
        #pragma unroll
        for (int j = 0; j < 6; j++)
            #pragma unroll
            for (int k = 0; k < 4; k++) acc[i][j][k] = 0.f;

    issue(0); issue(1); issue(2);

    for (int c = 0; c < 16; c++) {
        CPW2();
        __syncthreads();
        const uint32_t* Ab = (const uint32_t*)(smem + (c % 3) * G1_STAGE);
        const uint32_t* Bb = (const uint32_t*)(smem + (c % 3) * G1_STAGE + 8192);
        #pragma unroll
        for (int s = 0; s < 2; s++) {
            int c0 = (8 * s + tg)     ^ sw;
            int c1 = (8 * s + tg + 4) ^ sw;
            uint32_t af[4][4];
            #pragma unroll
            for (int fm = 0; fm < 4; fm++) {
                int base = (wm * 64 + fm * 16 + g) * 16;
                af[fm][0] = Ab[base + c0];
                af[fm][1] = Ab[base + 128 + c0];
                af[fm][2] = Ab[base + c1];
                af[fm][3] = Ab[base + 128 + c1];
            }
            #pragma unroll
            for (int fn = 0; fn < 6; fn++) {
                int col = (fn >> 1) * 64 + wn * 16 + ((fn & 1) << 3);
                int nb = (col + g) * 16;
                uint32_t b0 = Bb[nb + c0], b1 = Bb[nb + c1];
                #pragma unroll
                for (int fm = 0; fm < 4; fm++)
                    MMA_F16(acc[fm][fn], af[fm], b0, b1);
            }
        }
        __syncthreads();
        if (c + 3 < 16) issue(c + 3); else CPC();
    }

    // register-direct epilogue: thread holds i/f/h for rows (r, r+8), od pairs
    #pragma unroll
    for (int odp = 0; odp < 2; odp++) {
        int od = ob * 64 + wn * 16 + odp * 8 + 2 * tg;
        float2 bi = *(const float2*)(bias + od);
        float2 bf = *(const float2*)(bias + 256 + od);
        float2 bh = *(const float2*)(bias + 512 + od);
        #pragma unroll
        for (int fm = 0; fm < 4; fm++) {
            #pragma unroll
            for (int rsel = 0; rsel < 2; rsel++) {
                int m = m0 + wm * 64 + fm * 16 + g + rsel * 8;
                float iv0 = acc[fm][0 + odp][rsel * 2 + 0];
                float iv1 = acc[fm][0 + odp][rsel * 2 + 1];
                float fv0 = acc[fm][2 + odp][rsel * 2 + 0];
                float fv1 = acc[fm][2 + odp][rsel * 2 + 1];
                float hv0 = acc[fm][4 + odp][rsel * 2 + 0];
                float hv1 = acc[fm][4 + odp][rsel * 2 + 1];
                float2 fo, ig;
                fo.x = sigmoidf_(fv0 + bf.x);
                fo.y = sigmoidf_(fv1 + bf.y);
                ig.x = sigmoidf_(iv0 + bi.x) * fmaxf(hv0 + bh.x, 0.f);
                ig.y = sigmoidf_(iv1 + bi.y) * fmaxf(hv1 + bh.y, 0.f);
                *(float2*)(g_f    + (size_t)m * 256 + od) = fo;
                *(float2*)(g_cell + (size_t)m * 256 + od) = ig;
            }
        }
    }
}

// ---------------------------------------------------------------------------
// GEMM2 (mma.sync fp16 m16n8k16, cp.async 2-stage, 2 CTAs/SM): 128m x 128n.
// ---------------------------------------------------------------------------
#define G2_STAGE 16384              // 8192 A + 8192 B
#define G2_SMEM  (2*G2_STAGE)       // 32768 -> 2 CTAs/SM
__global__ __launch_bounds__(256, 2)
void gemm2_t(const float* __restrict__ bias, float* __restrict__ out)
{
    extern __shared__ char smem[];
    uint32_t sb = s2u(smem);

    int t = threadIdx.x, w = t >> 5, lane = t & 31;
    int g = lane >> 2, tg = lane & 3;
    int wm = w >> 2, wn = w & 3;
    int n0 = blockIdx.x * 128;
    int m0 = blockIdx.y * 128;
    int sw = (g & 6) << 1;

    const char* srcAh[2]; const char* srcAc[2]; const char* srcB[2];
    uint32_t dstQ[2];
    #pragma unroll
    for (int q = 0; q < 2; q++) {
        int gid = t + q * 256, row = gid >> 2, qc = gid & 3;
        srcAh[q] = (const char*)(g_headshf + (size_t)(m0 + row) * 256 + qc * 8);
        srcAc[q] = (const char*)(g_cellhf  + (size_t)(m0 + row) * 256 + qc * 8);
        srcB[q]  = (const char*)(g_Wog + (size_t)(n0 + row) * 512 + qc * 8);
        dstQ[q]  = row * 64 + ((qc << 4) ^ ((row & 6) << 3));
    }

    auto issue = [&](int c) {
        uint32_t base = sb + (c & 1) * G2_STAGE;
        int k0 = c * 32;
        if (k0 < 256) {
            #pragma unroll
            for (int q = 0; q < 2; q++) CPA(base + dstQ[q], srcAh[q] + (size_t)k0 * 2);
        } else {
            #pragma unroll
            for (int q = 0; q < 2; q++) CPA(base + dstQ[q], srcAc[q] + (size_t)(k0 - 256) * 2);
        }
        uint32_t bb = base + 8192;
        #pragma unroll
        for (int q = 0; q < 2; q++) CPA(bb + dstQ[q], srcB[q] + (size_t)k0 * 2);
        CPC();
    };

    float acc[4][4][4];
    #pragma unroll
    for (int i = 0; i < 4; i++)
        #pragma unroll
        for (int j = 0; j < 4; j++)
            #pragma unroll
            for (int k = 0; k < 4; k++) acc[i][j][k] = 0.f;

    issue(0); issue(1);

    for (int c = 0; c < 16; c++) {
        CPW1();
        __syncthreads();
        const uint32_t* Ab = (const uint32_t*)(smem + (c & 1) * G2_STAGE);
        const uint32_t* Bb = (const uint32_t*)(smem + (c & 1) * G2_STAGE + 8192);
        #pragma unroll
        for (int s = 0; s < 2; s++) {
            int c0 = (8 * s + tg)     ^ sw;
            int c1 = (8 * s + tg + 4) ^ sw;
            uint32_t af[4][4];
            #pragma unroll
            for (int fm = 0; fm < 4; fm++) {
                int base = (wm * 64 + fm * 16 + g) * 16;
                af[fm][0] = Ab[base + c0];
                af[fm][1] = Ab[base + 128 + c0];
                af[fm][2] = Ab[base + c1];
                af[fm][3] = Ab[base + 128 + c1];
            }
            #pragma unroll
            for (int fn = 0; fn < 4; fn++) {
                int nb = (wn * 32 + fn * 8 + g) * 16;
                uint32_t b0 = Bb[nb + c0], b1 = Bb[nb + c1];
                #pragma unroll
                for (int fm = 0; fm < 4; fm++)
                    MMA_F16(acc[fm][fn], af[fm], b0, b1);
            }
        }
        __syncthreads();
        if (c + 2 < 16) issue(c + 2); else CPC();
    }

    // register-direct epilogue
    #pragma unroll
    for (int fn = 0; fn < 4; fn++) {
        int od = n0 + wn * 32 + fn * 8 + 2 * tg;
        float2 bb = *(const float2*)(bias + od);
        #pragma unroll
        for (int fm = 0; fm < 4; fm++) {
            #pragma unroll
            for (int rsel = 0; rsel < 2; rsel++) {
                int m = m0 + wm * 64 + fm * 16 + g + rsel * 8;
                float2 cl = *(const float2*)(g_cell + (size_t)m * 256 + od);
                float2 v;
                v.x = sigmoidf_(acc[fm][fn][rsel * 2 + 0] + bb.x) * cl.x;
                v.y = sigmoidf_(acc[fm][fn][rsel * 2 + 1] + bb.y) * cl.y;
                *(float2*)(out + (size_t)m * 256 + od) = v;
            }
        }
    }
}

// ---------------------------------------------------------------------------
// Scan: c <- f*c + igh over S; writes exact cell and fp16 cell.
// ---------------------------------------------------------------------------
__global__ void scan_kernel(const float* __restrict__ init_cx) {
    int lane = threadIdx.x;
    int r    = threadIdx.y;
    int idt  = blockIdx.x & 7;
    int h    = (blockIdx.x >> 3) & 7;
    int b    = blockIdx.x >> 6;
    int od   = idt * 32 + lane;
    size_t base = (size_t)b * Ssz * SSTRIDE + (size_t)h * 256 + od;
    const int CH = Ssz / 16;

    size_t p = base + (size_t)(r * CH) * SSTRIDE;
    float F = 1.f, I = 0.f;
    #pragma unroll 8
    for (int i = 0; i < CH; i++) {
        float f = g_f[p], ig = g_cell[p];
        I = fmaf(f, I, ig);
        F *= f;
        p += SSTRIDE;
    }
    __shared__ float sF[16][32], sI[16][32];
    sF[r][lane] = F; sI[r][lane] = I;
    __syncthreads();
    if (r == 0) {
        float c = init_cx[h * 256 + od];
        #pragma unroll
        for (int k2 = 0; k2 < 16; k2++) {
            float nf = sF[k2][lane], ni = sI[k2][lane];
            sI[k2][lane] = c;
            c = fmaf(nf, c, ni);
        }
    }
    __syncthreads();
    float c = sI[r][lane];
    p = base + (size_t)(r * CH) * SSTRIDE;
    #pragma unroll 8
    for (int i = 0; i < CH; i++) {
        float f = g_f[p], ig = g_cell[p];
        c = fmaf(f, c, ig);
        g_cell[p] = c;
        g_cellhf[p] = __float2half_rn(c);
        p += SSTRIDE;
    }
}

// ---------------------------------------------------------------------------
extern "C" void kernel_launch(void* const* d_in, const int* in_sizes, int n_in,
                              void* d_out, int out_size)
{
    const float* heads   = (const float*)d_in[0];
    const float* W_hid   = (const float*)d_in[1];
    const float* b_hid   = (const float*)d_in[2];
    const float* W_og    = (const float*)d_in[3];
    const float* b_og    = (const float*)d_in[4];
    const float* ln_w    = (const float*)d_in[5];
    const float* ln_b    = (const float*)d_in[6];
    const float* init_cx = (const float*)d_in[7];
    float* out = (float*)d_out;

    cudaFuncSetAttribute(gemm1_t, cudaFuncAttributeMaxDynamicSharedMemorySize, G1_SMEM);
    cudaFuncSetAttribute(gemm2_t, cudaFuncAttributeMaxDynamicSharedMemorySize, G2_SMEM);

    repack_kernel<<<768, 128>>>(W_hid);
    repack_og<<<256, 128>>>(W_og);
    cumsum_kernel<<<512, dim3(32, 16)>>>(heads);
    stats_kernel<<<BSN, 256>>>(ln_w, ln_b);
    gemm1_t<<<dim3(4, Mrows / 128), 256, G1_SMEM>>>(b_hid);
    scan_kernel<<<512, dim3(32, 16)>>>(init_cx);
    gemm2_t<<<dim3(2, Mrows / 128), 256, G2_SMEM>>>(b_og, out);
}